// round 5
// baseline (speedup 1.0000x reference)
#include <cuda_runtime.h>

#define HH 64
#define WW 64
#define HWSZ 4096
#define CCH 64

// ---- device scratch (allocation-free rule) ----
__device__ float g_off [2 * 296 * HWSZ];
__device__ float g_tmp [4 * CCH * 2 * HWSZ];
__device__ float g_part[8 * 2 * 128 * HWSZ];
__device__ float g_wt  [524288];

// ---- packed f32x2 helpers ----
__device__ __forceinline__ unsigned long long pk2(float lo, float hi) {
    unsigned long long r;
    asm("mov.b64 %0, {%1, %2};" : "=l"(r) : "f"(lo), "f"(hi));
    return r;
}
__device__ __forceinline__ void fma2(unsigned long long& d, unsigned long long a,
                                     unsigned long long b) {
    asm("fma.rn.f32x2 %0, %1, %2, %3;" : "=l"(d) : "l"(a), "l"(b), "l"(d));
}
__device__ __forceinline__ void unpk2(unsigned long long v, float& lo, float& hi) {
    asm("mov.b64 {%0, %1}, %2;" : "=f"(lo), "=f"(hi) : "l"(v));
}
__device__ __forceinline__ unsigned long long mul2(unsigned long long a,
                                                   unsigned long long b) {
    unsigned long long r;
    asm("mul.rn.f32x2 %0, %1, %2;" : "=l"(r) : "l"(a), "l"(b));
    return r;
}

// ---------------------------------------------------------------------------
// Fused weight transpose: wv[O][64][K][K] -> wt[tap][O]
// ---------------------------------------------------------------------------
__global__ void wtrans_all(const float* __restrict__ w0,
                           const float* __restrict__ w1,
                           const float* __restrict__ w2,
                           const float* __restrict__ w3,
                           float* __restrict__ wt)
{
    int idx = blockIdx.x * 256 + threadIdx.x;
    const int n0 = 18 * 576, n1 = 50 * 1600, n2 = 50 * 1600, n3 = 98 * 3136;
    const float* src; int O, taps; float* dst;
    if (idx < n0)                { src = w0; O = 18; taps = 576;  dst = wt; }
    else if ((idx -= n0) < n1)   { src = w1; O = 50; taps = 1600; dst = wt + n0; }
    else if ((idx -= n1) < n2)   { src = w2; O = 50; taps = 1600; dst = wt + n0 + n1; }
    else if ((idx -= n2) < n3)   { src = w3; O = 98; taps = 3136; dst = wt + n0 + n1 + n2; }
    else return;
    int o = idx / taps;
    int t = idx - o * taps;
    dst[(size_t)t * O + o] = src[idx];
}

// ---------------------------------------------------------------------------
// Offset conv implicit GEMM, f32x2. Transposed X-panel: XP[i][col] packs the
// 4 output rows' samples for tap-row i, so one LDS.128 yields both f32x2
// operands with zero packing instructions.
// Block 256 thr; tile 32 oc x (4 rows x 64 cols); per-thread 8 oc x 2 f32x2.
// grid = (16 hblk, ceil(O/32), 2*ns). Partials [sp][b][O][HWSZ] (no bias).
// ---------------------------------------------------------------------------
template<int K, int DIL, int PAD>
__global__ void offconv_gemm(const float* __restrict__ src, int srcC, int coff,
                             const float* __restrict__ wt, int O, int ns,
                             float* __restrict__ part)
{
    constexpr int KK   = K * K;
    constexpr int WPAD = 64 + 2 * PAD;

    __shared__ float4 XP[K][WPAD];      // [tap_row][padded col] -> rows 0..3
    __shared__ float2 WS2[KK][32];      // duplicated weights

    const int tid  = threadIdx.x;
    const int lane = tid & 63;
    const int og   = tid >> 6;
    const int h0   = blockIdx.x * 4;
    const int o0   = blockIdx.y * 32;
    const int b    = blockIdx.z / ns;
    const int sp   = blockIdx.z % ns;
    const int cchunk = CCH / ns;
    const int cbeg = sp * cchunk;
    const int cend = cbeg + cchunk;

    unsigned long long acc[8][2];
    #pragma unroll
    for (int oc = 0; oc < 8; ++oc) { acc[oc][0] = 0ull; acc[oc][1] = 0ull; }

    for (int c = cbeg; c < cend; ++c) {
        const float* sc = src + (((size_t)b * srcC + coff + c) << 12);
        const float* wc = wt + (size_t)c * KK * O;
        __syncthreads();
        // stage transposed X panel
        for (int idx = tid; idx < K * WPAD; idx += 256) {
            const int i   = idx / WPAD;
            const int s   = idx - i * WPAD;
            const int yy  = h0 - PAD + i * DIL;
            const int col = s - PAD;
            float4 v = make_float4(0.f, 0.f, 0.f, 0.f);
            if ((unsigned)col < 64u) {
                const float* p = sc + yy * 64 + col;
                if ((unsigned)(yy)     < 64u) v.x = p[0];
                if ((unsigned)(yy + 1) < 64u) v.y = p[64];
                if ((unsigned)(yy + 2) < 64u) v.z = p[128];
                if ((unsigned)(yy + 3) < 64u) v.w = p[192];
            }
            XP[i][s] = v;
        }
        // stage duplicated weights
        for (int idx = tid; idx < KK * 32; idx += 256) {
            const int tap = idx >> 5;
            const int oc  = idx & 31;
            const int o   = o0 + oc;
            const float w = (o < O) ? wc[tap * O + o] : 0.f;
            WS2[tap][oc] = make_float2(w, w);
        }
        __syncthreads();

        #pragma unroll 1
        for (int i = 0; i < K; ++i) {
            #pragma unroll
            for (int j = 0; j < K; ++j) {
                const ulonglong2* wrow = (const ulonglong2*)&WS2[i * K + j][og * 8];
                const ulonglong2 wq0 = wrow[0];
                const ulonglong2 wq1 = wrow[1];
                const ulonglong2 wq2 = wrow[2];
                const ulonglong2 wq3 = wrow[3];
                const ulonglong2 xv = *(const ulonglong2*)&XP[i][lane + j * DIL];
                fma2(acc[0][0], wq0.x, xv.x);  fma2(acc[0][1], wq0.x, xv.y);
                fma2(acc[1][0], wq0.y, xv.x);  fma2(acc[1][1], wq0.y, xv.y);
                fma2(acc[2][0], wq1.x, xv.x);  fma2(acc[2][1], wq1.x, xv.y);
                fma2(acc[3][0], wq1.y, xv.x);  fma2(acc[3][1], wq1.y, xv.y);
                fma2(acc[4][0], wq2.x, xv.x);  fma2(acc[4][1], wq2.x, xv.y);
                fma2(acc[5][0], wq2.y, xv.x);  fma2(acc[5][1], wq2.y, xv.y);
                fma2(acc[6][0], wq3.x, xv.x);  fma2(acc[6][1], wq3.x, xv.y);
                fma2(acc[7][0], wq3.y, xv.x);  fma2(acc[7][1], wq3.y, xv.y);
            }
        }
    }

    float* pb = part + (((size_t)sp * 2 + b) * O) * HWSZ;
    #pragma unroll
    for (int oc = 0; oc < 8; ++oc) {
        const int o = o0 + og * 8 + oc;
        if (o < O) {
            float r0, r1, r2, r3;
            unpk2(acc[oc][0], r0, r1);
            unpk2(acc[oc][1], r2, r3);
            float* po = pb + (size_t)o * HWSZ + h0 * 64 + lane;
            po[0]   = r0;
            po[64]  = r1;
            po[128] = r2;
            po[192] = r3;
        }
    }
}

// combine: out[b,o,p] = bias[o] + sum_sp part[sp][b][o][p]   (float4)
__global__ void combine_kernel(const float* __restrict__ part,
                               const float* __restrict__ bias,
                               int O, int ns, float* __restrict__ out)
{
    const int p = blockIdx.x * 256 + threadIdx.x;
    const int o = blockIdx.y;
    const int b = blockIdx.z;
    const float bs = bias[o];
    float4 s = make_float4(bs, bs, bs, bs);
    for (int sp = 0; sp < ns; ++sp) {
        const float4 v = ((const float4*)part)[(((size_t)sp * 2 + b) * O + o) * 1024 + p];
        s.x += v.x; s.y += v.y; s.z += v.z; s.w += v.w;
    }
    ((float4*)out)[((size_t)b * O + o) * 1024 + p] = s;
}

// ---------------------------------------------------------------------------
// Deformable depthwise conv: index math once per tap, 2 channels per block.
// Block 256 thr (4 rows x 64 cols); grid (16, 32 cgroups, 2) = 1024 blocks.
// Tap loop unrolled x2 for gather MLP.
// ---------------------------------------------------------------------------
template<int KS, int DIL, int PAD>
__global__ void deform_kernel(const float* __restrict__ src, int srcC, int coff,
                              const float* __restrict__ off,
                              const float* __restrict__ dw,
                              float* __restrict__ out)
{
    constexpr int K = KS * KS;
    __shared__ float sdw[2][K];

    const int tid = threadIdx.x;
    const int w   = tid & 63;
    const int r   = tid >> 6;
    const int h   = blockIdx.x * 4 + r;
    const int cg  = blockIdx.y;
    const int b   = blockIdx.z;

    if (tid < 2 * K) sdw[tid / K][tid % K] = dw[(cg * 2 + tid / K) * K + tid % K];
    __syncthreads();

    const float* xb = src + ((size_t)b * srcC + coff + cg * 2) * HWSZ;
    const float* ob = off + (size_t)b * (2 * K) * HWSZ + h * WW + w;

    float acc0 = 0.f, acc1 = 0.f;

    #pragma unroll 2
    for (int kidx = 0; kidx < K; ++kidx) {
        const float oy = ob[(2 * kidx)     * HWSZ];
        const float ox = ob[(2 * kidx + 1) * HWSZ];
        const float py = oy + (float)(h - PAD + (kidx / KS) * DIL);
        const float px = ox + (float)(w - PAD + (kidx % KS) * DIL);
        const int   y0 = __float2int_rd(py);
        const int   x0 = __float2int_rd(px);
        const float ly = py - (float)y0;
        const float lx = px - (float)x0;
        const float hy = 1.f - ly;
        const float hx = 1.f - lx;

        const float m_y0 = ((unsigned)y0       < 64u) ? 1.f : 0.f;
        const float m_y1 = ((unsigned)(y0 + 1) < 64u) ? 1.f : 0.f;
        const float m_x0 = ((unsigned)x0       < 64u) ? 1.f : 0.f;
        const float m_x1 = ((unsigned)(x0 + 1) < 64u) ? 1.f : 0.f;

        const int yc0 = min(max(y0, 0), 63);
        const int yc1 = min(max(y0 + 1, 0), 63);
        const int xc0 = min(max(x0, 0), 63);
        const int xc1 = min(max(x0 + 1, 0), 63);

        const int i00 = yc0 * 64 + xc0;
        const int i01 = yc0 * 64 + xc1;
        const int i10 = yc1 * 64 + xc0;
        const int i11 = yc1 * 64 + xc1;

        const float w00 = hy * hx * (m_y0 * m_x0);
        const float w01 = hy * lx * (m_y0 * m_x1);
        const float w10 = ly * hx * (m_y1 * m_x0);
        const float w11 = ly * lx * (m_y1 * m_x1);

        {
            float v = xb[i00] * w00;
            v = fmaf(xb[i01], w01, v);
            v = fmaf(xb[i10], w10, v);
            v = fmaf(xb[i11], w11, v);
            acc0 = fmaf(v, sdw[0][kidx], acc0);
        }
        {
            const float* xc = xb + HWSZ;
            float v = xc[i00] * w00;
            v = fmaf(xc[i01], w01, v);
            v = fmaf(xc[i10], w10, v);
            v = fmaf(xc[i11], w11, v);
            acc1 = fmaf(v, sdw[1][kidx], acc1);
        }
    }

    float* po = out + ((size_t)b * CCH + cg * 2) * HWSZ + h * WW + w;
    po[0]    = acc0;
    po[HWSZ] = acc1;
}

// ---------------------------------------------------------------------------
// 1x1 conv fused with gating, f32x2: each thread = 2 adjacent pixels.
// ---------------------------------------------------------------------------
__global__ void conv1x1_gate_kernel(const float* __restrict__ in,
                                    const float* __restrict__ wv,
                                    const float* __restrict__ bias,
                                    const float* __restrict__ x,
                                    int xcoff, float* __restrict__ out)
{
    __shared__ float2 wdup[CCH];
    const int tid = threadIdx.x;
    const int o   = blockIdx.y;
    const int b   = blockIdx.z;
    const int px0 = blockIdx.x * 512 + tid * 2;

    if (tid < CCH) {
        const float wv_ = wv[o * CCH + tid];
        wdup[tid] = make_float2(wv_, wv_);
    }
    __syncthreads();

    const float bs = bias[o];
    unsigned long long acc = pk2(bs, bs);
    const char* ib = (const char*)(in + (size_t)b * CCH * HWSZ + px0);
    #pragma unroll
    for (int c = 0; c < CCH; ++c) {
        const unsigned long long iv = *(const unsigned long long*)(ib + (size_t)c * (HWSZ * 4));
        const unsigned long long wq = *(const unsigned long long*)&wdup[c];
        fma2(acc, wq, iv);
    }

    const size_t oi = ((size_t)b * 128 + xcoff + o) * HWSZ + px0;
    const unsigned long long xv = *(const unsigned long long*)(x + oi);
    *(unsigned long long*)(out + oi) = mul2(acc, xv);
}

// ---------------------------------------------------------------------------
extern "C" void kernel_launch(void* const* d_in, const int* in_sizes, int n_in,
                              void* d_out, int out_size)
{
    const float* x          = (const float*)d_in[0];
    const float* cv0_off_w  = (const float*)d_in[1];
    const float* cv0_off_b  = (const float*)d_in[2];
    const float* cv0_w      = (const float*)d_in[3];
    const float* cvs_off_w  = (const float*)d_in[4];
    const float* cvs_off_b  = (const float*)d_in[5];
    const float* cvs_w      = (const float*)d_in[6];
    const float* c0_off_w   = (const float*)d_in[7];
    const float* c0_off_b   = (const float*)d_in[8];
    const float* c0_w       = (const float*)d_in[9];
    const float* cs_off_w   = (const float*)d_in[10];
    const float* cs_off_b   = (const float*)d_in[11];
    const float* cs_w       = (const float*)d_in[12];
    const float* conv1_w    = (const float*)d_in[13];
    const float* conv1_b    = (const float*)d_in[14];
    const float* conv2_w    = (const float*)d_in[15];
    const float* conv2_b    = (const float*)d_in[16];
    float* out = (float*)d_out;

    static cudaStream_t s2 = nullptr;
    static cudaEvent_t evRoot = nullptr, evJoin = nullptr;
    if (!s2) {
        cudaStreamCreateWithFlags(&s2, cudaStreamNonBlocking);
        cudaEventCreateWithFlags(&evRoot, cudaEventDisableTiming);
        cudaEventCreateWithFlags(&evJoin, cudaEventDisableTiming);
    }

    float *offb, *tmp, *part, *wt;
    cudaGetSymbolAddress((void**)&offb, g_off);
    cudaGetSymbolAddress((void**)&tmp,  g_tmp);
    cudaGetSymbolAddress((void**)&part, g_part);
    cudaGetSymbolAddress((void**)&wt,   g_wt);

    float* off0  = offb;
    float* off1  = offb + (size_t)2 * 100 * HWSZ;
    float* t0a   = tmp;
    float* t1a   = tmp + (size_t)1 * CCH * 2 * HWSZ;
    float* t0b   = tmp + (size_t)2 * CCH * 2 * HWSZ;
    float* t1b   = tmp + (size_t)3 * CCH * 2 * HWSZ;
    float* part0 = part;
    float* part1 = part + (size_t)4 * 1024 * 1024;

    const int taps3 = 576, taps5 = 1600, taps7 = 3136;
    float* wt_cv0 = wt;
    float* wt_cvs = wt_cv0 + 18 * taps3;
    float* wt_c0  = wt_cvs + 50 * taps5;
    float* wt_cs  = wt_c0  + 50 * taps5;

    dim3 b256(256);
    const int n_all = 18 * taps3 + 50 * taps5 + 50 * taps5 + 98 * taps7;
    wtrans_all<<<(n_all + 255) / 256, b256>>>(cv0_off_w, cvs_off_w, c0_off_w, cs_off_w, wt);

    cudaEventRecord(evRoot, 0);
    cudaStreamWaitEvent(s2, evRoot, 0);

    // ---- Branch 0 (stream 0): channels [0,64) ----
    offconv_gemm<3,1,1><<<dim3(16, 1, 2 * 16), b256>>>(x, 128, 0, wt_cv0, 18, 16, part0);
    combine_kernel<<<dim3(4, 18, 2), b256>>>(part0, cv0_off_b, 18, 16, off0);
    deform_kernel<3,1,1><<<dim3(16, 32, 2), b256>>>(x, 128, 0, off0, cv0_w, t0a);

    offconv_gemm<5,3,6><<<dim3(16, 2, 2 * 8), b256>>>(t0a, 64, 0, wt_cvs, 50, 8, part0);
    combine_kernel<<<dim3(4, 50, 2), b256>>>(part0, cvs_off_b, 50, 8, off0);
    deform_kernel<5,3,6><<<dim3(16, 32, 2), b256>>>(t0a, 64, 0, off0, cvs_w, t1a);

    conv1x1_gate_kernel<<<dim3(8, 64, 2), b256>>>(t1a, conv1_w, conv1_b, x, 0, out);

    // ---- Branch 1 (stream s2): channels [64,128) ----
    offconv_gemm<5,1,2><<<dim3(16, 2, 2 * 8), b256, 0, s2>>>(x, 128, 64, wt_c0, 50, 8, part1);
    combine_kernel<<<dim3(4, 50, 2), b256, 0, s2>>>(part1, c0_off_b, 50, 8, off1);
    deform_kernel<5,1,2><<<dim3(16, 32, 2), b256, 0, s2>>>(x, 128, 64, off1, c0_w, t0b);

    offconv_gemm<7,3,9><<<dim3(16, 4, 2 * 4), b256, 0, s2>>>(t0b, 64, 0, wt_cs, 98, 4, part1);
    combine_kernel<<<dim3(4, 98, 2), b256, 0, s2>>>(part1, cs_off_b, 98, 4, off1);
    deform_kernel<7,3,9><<<dim3(16, 32, 2), b256, 0, s2>>>(t0b, 64, 0, off1, cs_w, t1b);

    conv1x1_gate_kernel<<<dim3(8, 64, 2), b256, 0, s2>>>(t1b, conv2_w, conv2_b, x, 64, out);

    cudaEventRecord(evJoin, s2);
    cudaStreamWaitEvent(0, evJoin, 0);
}

// round 6
// speedup vs baseline: 1.0624x; 1.0624x over previous
#include <cuda_runtime.h>

#define HH 64
#define WW 64
#define HWSZ 4096
#define CCH 64

// ---- device scratch (allocation-free rule) ----
__device__ float g_tmp [4 * CCH * 2 * HWSZ];
__device__ float g_part[8 * 2 * 128 * HWSZ];
__device__ float g_wt  [524288];
__device__ int4   g_bidx0[2 * 25 * HWSZ];   // branch0 bilinear indices (max K=25)
__device__ float4 g_bw0  [2 * 25 * HWSZ];   // branch0 bilinear weights
__device__ int4   g_bidx1[2 * 49 * HWSZ];   // branch1 (max K=49)
__device__ float4 g_bw1  [2 * 49 * HWSZ];

// ---- packed f32x2 helpers ----
__device__ __forceinline__ unsigned long long pk2(float lo, float hi) {
    unsigned long long r;
    asm("mov.b64 %0, {%1, %2};" : "=l"(r) : "f"(lo), "f"(hi));
    return r;
}
__device__ __forceinline__ void fma2(unsigned long long& d, unsigned long long a,
                                     unsigned long long b) {
    asm("fma.rn.f32x2 %0, %1, %2, %3;" : "=l"(d) : "l"(a), "l"(b), "l"(d));
}
__device__ __forceinline__ void unpk2(unsigned long long v, float& lo, float& hi) {
    asm("mov.b64 {%0, %1}, %2;" : "=f"(lo), "=f"(hi) : "l"(v));
}
__device__ __forceinline__ unsigned long long mul2(unsigned long long a,
                                                   unsigned long long b) {
    unsigned long long r;
    asm("mul.rn.f32x2 %0, %1, %2;" : "=l"(r) : "l"(a), "l"(b));
    return r;
}

// ---------------------------------------------------------------------------
// Fused weight transpose: wv[O][64][K][K] -> wt[tap][O]
// ---------------------------------------------------------------------------
__global__ void wtrans_all(const float* __restrict__ w0,
                           const float* __restrict__ w1,
                           const float* __restrict__ w2,
                           const float* __restrict__ w3,
                           float* __restrict__ wt)
{
    int idx = blockIdx.x * 256 + threadIdx.x;
    const int n0 = 18 * 576, n1 = 50 * 1600, n2 = 50 * 1600, n3 = 98 * 3136;
    const float* src; int O, taps; float* dst;
    if (idx < n0)                { src = w0; O = 18; taps = 576;  dst = wt; }
    else if ((idx -= n0) < n1)   { src = w1; O = 50; taps = 1600; dst = wt + n0; }
    else if ((idx -= n1) < n2)   { src = w2; O = 50; taps = 1600; dst = wt + n0 + n1; }
    else if ((idx -= n2) < n3)   { src = w3; O = 98; taps = 3136; dst = wt + n0 + n1 + n2; }
    else return;
    int o = idx / taps;
    int t = idx - o * taps;
    dst[(size_t)t * O + o] = src[idx];
}

// ---------------------------------------------------------------------------
// Offset conv implicit GEMM, f32x2 (R4 form: scalar XS rows + pk2).
// Block 256 thr; tile 32 oc x (4 rows x 64 cols); per-thread 8 oc x 2 f32x2.
// grid = (16 hblk, ceil(O/32), 2*ns). Partials [sp][b][O][HWSZ] (no bias).
// ---------------------------------------------------------------------------
template<int K, int DIL, int PAD>
__global__ void offconv_gemm(const float* __restrict__ src, int srcC, int coff,
                             const float* __restrict__ wt, int O, int ns,
                             float* __restrict__ part)
{
    constexpr int KK     = K * K;
    constexpr int WPAD   = 64 + 2 * PAD;
    constexpr int ROWS_X = 4 + (K - 1) * DIL;

    __shared__ float  XS[ROWS_X][WPAD];
    __shared__ float2 WS2[KK][32];

    const int tid  = threadIdx.x;
    const int lane = tid & 63;
    const int og   = tid >> 6;
    const int h0   = blockIdx.x * 4;
    const int o0   = blockIdx.y * 32;
    const int b    = blockIdx.z / ns;
    const int sp   = blockIdx.z % ns;
    const int cchunk = CCH / ns;
    const int cbeg = sp * cchunk;
    const int cend = cbeg + cchunk;

    unsigned long long acc[8][2];
    #pragma unroll
    for (int oc = 0; oc < 8; ++oc) { acc[oc][0] = 0ull; acc[oc][1] = 0ull; }

    for (int c = cbeg; c < cend; ++c) {
        const float* sc = src + (((size_t)b * srcC + coff + c) << 12);
        const float* wc = wt + (size_t)c * KK * O;
        __syncthreads();
        for (int idx = tid; idx < ROWS_X * WPAD; idx += 256) {
            const int rr  = idx / WPAD;
            const int s   = idx - rr * WPAD;
            const int yy  = h0 - PAD + rr;
            const int col = s - PAD;
            float v = 0.f;
            if ((unsigned)yy < 64u && (unsigned)col < 64u) v = sc[yy * 64 + col];
            XS[rr][s] = v;
        }
        for (int idx = tid; idx < KK * 32; idx += 256) {
            const int tap = idx >> 5;
            const int oc  = idx & 31;
            const int o   = o0 + oc;
            const float w = (o < O) ? wc[tap * O + o] : 0.f;
            WS2[tap][oc] = make_float2(w, w);
        }
        __syncthreads();

        #pragma unroll 1
        for (int i = 0; i < K; ++i) {
            const int ri = i * DIL;
            #pragma unroll
            for (int j = 0; j < K; ++j) {
                const ulonglong2* wrow = (const ulonglong2*)&WS2[i * K + j][og * 8];
                const ulonglong2 wq0 = wrow[0];
                const ulonglong2 wq1 = wrow[1];
                const ulonglong2 wq2 = wrow[2];
                const ulonglong2 wq3 = wrow[3];
                const int sx = lane + j * DIL;
                const unsigned long long xa = pk2(XS[ri + 0][sx], XS[ri + 1][sx]);
                const unsigned long long xb = pk2(XS[ri + 2][sx], XS[ri + 3][sx]);
                fma2(acc[0][0], wq0.x, xa);  fma2(acc[0][1], wq0.x, xb);
                fma2(acc[1][0], wq0.y, xa);  fma2(acc[1][1], wq0.y, xb);
                fma2(acc[2][0], wq1.x, xa);  fma2(acc[2][1], wq1.x, xb);
                fma2(acc[3][0], wq1.y, xa);  fma2(acc[3][1], wq1.y, xb);
                fma2(acc[4][0], wq2.x, xa);  fma2(acc[4][1], wq2.x, xb);
                fma2(acc[5][0], wq2.y, xa);  fma2(acc[5][1], wq2.y, xb);
                fma2(acc[6][0], wq3.x, xa);  fma2(acc[6][1], wq3.x, xb);
                fma2(acc[7][0], wq3.y, xa);  fma2(acc[7][1], wq3.y, xb);
            }
        }
    }

    float* pb = part + (((size_t)sp * 2 + b) * O) * HWSZ;
    #pragma unroll
    for (int oc = 0; oc < 8; ++oc) {
        const int o = o0 + og * 8 + oc;
        if (o < O) {
            float r0, r1, r2, r3;
            unpk2(acc[oc][0], r0, r1);
            unpk2(acc[oc][1], r2, r3);
            float* po = pb + (size_t)o * HWSZ + h0 * 64 + lane;
            po[0]   = r0;
            po[64]  = r1;
            po[128] = r2;
            po[192] = r3;
        }
    }
}

// ---------------------------------------------------------------------------
// Fused combine + bilinear prep: reduces partial slabs for the (oy,ox) pair
// of tap k, adds bias, and emits clamped corner indices + masked weights.
// grid (16, K, 2), block 256.
// ---------------------------------------------------------------------------
template<int KS, int DIL, int PAD>
__global__ void combine_bilin(const float* __restrict__ part,
                              const float* __restrict__ bias,
                              int O, int ns,
                              int4* __restrict__ bidx, float4* __restrict__ bw)
{
    constexpr int K = KS * KS;
    const int p = blockIdx.x * 256 + threadIdx.x;
    const int k = blockIdx.y;
    const int b = blockIdx.z;

    float oy = bias[2 * k];
    float ox = bias[2 * k + 1];
    for (int sp = 0; sp < ns; ++sp) {
        const float* pb = part + (((size_t)sp * 2 + b) * O) * HWSZ + p;
        oy += pb[(size_t)(2 * k)     * HWSZ];
        ox += pb[(size_t)(2 * k + 1) * HWSZ];
    }

    const int h = p >> 6;
    const int w = p & 63;
    const float py = oy + (float)(h - PAD + (k / KS) * DIL);
    const float px = ox + (float)(w - PAD + (k % KS) * DIL);
    const int   y0 = __float2int_rd(py);
    const int   x0 = __float2int_rd(px);
    const float ly = py - (float)y0;
    const float lx = px - (float)x0;
    const float hy = 1.f - ly;
    const float hx = 1.f - lx;

    const float m_y0 = ((unsigned)y0       < 64u) ? 1.f : 0.f;
    const float m_y1 = ((unsigned)(y0 + 1) < 64u) ? 1.f : 0.f;
    const float m_x0 = ((unsigned)x0       < 64u) ? 1.f : 0.f;
    const float m_x1 = ((unsigned)(x0 + 1) < 64u) ? 1.f : 0.f;

    const int yc0 = min(max(y0, 0), 63);
    const int yc1 = min(max(y0 + 1, 0), 63);
    const int xc0 = min(max(x0, 0), 63);
    const int xc1 = min(max(x0 + 1, 0), 63);

    const size_t o = ((size_t)b * K + k) * HWSZ + p;
    bidx[o] = make_int4(yc0 * 64 + xc0, yc0 * 64 + xc1,
                        yc1 * 64 + xc0, yc1 * 64 + xc1);
    bw[o]   = make_float4(hy * hx * (m_y0 * m_x0), hy * lx * (m_y0 * m_x1),
                          ly * hx * (m_y1 * m_x0), ly * lx * (m_y1 * m_x1));
}

// ---------------------------------------------------------------------------
// Deform apply: gathers + weighted sum only; 2 channels per block.
// Block 256 thr; grid (16, 32 cgroups, 2) = 1024 blocks.
// ---------------------------------------------------------------------------
template<int K>
__global__ void deform_apply(const float* __restrict__ src, int srcC, int coff,
                             const int4* __restrict__ bidx,
                             const float4* __restrict__ bw,
                             const float* __restrict__ dw,
                             float* __restrict__ out)
{
    __shared__ float sdw[2][K];
    const int tid = threadIdx.x;
    const int p   = blockIdx.x * 256 + tid;
    const int cg  = blockIdx.y;
    const int b   = blockIdx.z;

    if (tid < 2 * K) sdw[tid / K][tid % K] = dw[(cg * 2 + tid / K) * K + tid % K];
    __syncthreads();

    const float* xb = src + ((size_t)b * srcC + coff + cg * 2) * HWSZ;
    const float* xc = xb + HWSZ;
    const int4*   ib = bidx + (size_t)b * K * HWSZ + p;
    const float4* wb = bw   + (size_t)b * K * HWSZ + p;

    float acc0 = 0.f, acc1 = 0.f;
    #pragma unroll 2
    for (int k = 0; k < K; ++k) {
        const int4   ii = ib[(size_t)k * HWSZ];
        const float4 wv = wb[(size_t)k * HWSZ];
        {
            float v = xb[ii.x] * wv.x;
            v = fmaf(xb[ii.y], wv.y, v);
            v = fmaf(xb[ii.z], wv.z, v);
            v = fmaf(xb[ii.w], wv.w, v);
            acc0 = fmaf(v, sdw[0][k], acc0);
        }
        {
            float v = xc[ii.x] * wv.x;
            v = fmaf(xc[ii.y], wv.y, v);
            v = fmaf(xc[ii.z], wv.z, v);
            v = fmaf(xc[ii.w], wv.w, v);
            acc1 = fmaf(v, sdw[1][k], acc1);
        }
    }

    float* po = out + ((size_t)b * CCH + cg * 2) * HWSZ + p;
    po[0]    = acc0;
    po[HWSZ] = acc1;
}

// ---------------------------------------------------------------------------
// 1x1 conv fused with gating, f32x2: each thread = 2 adjacent pixels.
// ---------------------------------------------------------------------------
__global__ void conv1x1_gate_kernel(const float* __restrict__ in,
                                    const float* __restrict__ wv,
                                    const float* __restrict__ bias,
                                    const float* __restrict__ x,
                                    int xcoff, float* __restrict__ out)
{
    __shared__ float2 wdup[CCH];
    const int tid = threadIdx.x;
    const int o   = blockIdx.y;
    const int b   = blockIdx.z;
    const int px0 = blockIdx.x * 512 + tid * 2;

    if (tid < CCH) {
        const float wv_ = wv[o * CCH + tid];
        wdup[tid] = make_float2(wv_, wv_);
    }
    __syncthreads();

    const float bs = bias[o];
    unsigned long long acc = pk2(bs, bs);
    const char* ib = (const char*)(in + (size_t)b * CCH * HWSZ + px0);
    #pragma unroll
    for (int c = 0; c < CCH; ++c) {
        const unsigned long long iv = *(const unsigned long long*)(ib + (size_t)c * (HWSZ * 4));
        const unsigned long long wq = *(const unsigned long long*)&wdup[c];
        fma2(acc, wq, iv);
    }

    const size_t oi = ((size_t)b * 128 + xcoff + o) * HWSZ + px0;
    const unsigned long long xv = *(const unsigned long long*)(x + oi);
    *(unsigned long long*)(out + oi) = mul2(acc, xv);
}

// ---------------------------------------------------------------------------
extern "C" void kernel_launch(void* const* d_in, const int* in_sizes, int n_in,
                              void* d_out, int out_size)
{
    const float* x          = (const float*)d_in[0];
    const float* cv0_off_w  = (const float*)d_in[1];
    const float* cv0_off_b  = (const float*)d_in[2];
    const float* cv0_w      = (const float*)d_in[3];
    const float* cvs_off_w  = (const float*)d_in[4];
    const float* cvs_off_b  = (const float*)d_in[5];
    const float* cvs_w      = (const float*)d_in[6];
    const float* c0_off_w   = (const float*)d_in[7];
    const float* c0_off_b   = (const float*)d_in[8];
    const float* c0_w       = (const float*)d_in[9];
    const float* cs_off_w   = (const float*)d_in[10];
    const float* cs_off_b   = (const float*)d_in[11];
    const float* cs_w       = (const float*)d_in[12];
    const float* conv1_w    = (const float*)d_in[13];
    const float* conv1_b    = (const float*)d_in[14];
    const float* conv2_w    = (const float*)d_in[15];
    const float* conv2_b    = (const float*)d_in[16];
    float* out = (float*)d_out;

    static cudaStream_t s2 = nullptr;
    static cudaEvent_t evRoot = nullptr, evJoin = nullptr;
    if (!s2) {
        cudaStreamCreateWithFlags(&s2, cudaStreamNonBlocking);
        cudaEventCreateWithFlags(&evRoot, cudaEventDisableTiming);
        cudaEventCreateWithFlags(&evJoin, cudaEventDisableTiming);
    }

    float *tmp, *part, *wt;
    int4 *bidx0, *bidx1;
    float4 *bw0, *bw1;
    cudaGetSymbolAddress((void**)&tmp,   g_tmp);
    cudaGetSymbolAddress((void**)&part,  g_part);
    cudaGetSymbolAddress((void**)&wt,    g_wt);
    cudaGetSymbolAddress((void**)&bidx0, g_bidx0);
    cudaGetSymbolAddress((void**)&bw0,   g_bw0);
    cudaGetSymbolAddress((void**)&bidx1, g_bidx1);
    cudaGetSymbolAddress((void**)&bw1,   g_bw1);

    float* t0a   = tmp;
    float* t1a   = tmp + (size_t)1 * CCH * 2 * HWSZ;
    float* t0b   = tmp + (size_t)2 * CCH * 2 * HWSZ;
    float* t1b   = tmp + (size_t)3 * CCH * 2 * HWSZ;
    float* part0 = part;
    float* part1 = part + (size_t)4 * 1024 * 1024;

    const int taps3 = 576, taps5 = 1600, taps7 = 3136;
    float* wt_cv0 = wt;
    float* wt_cvs = wt_cv0 + 18 * taps3;
    float* wt_c0  = wt_cvs + 50 * taps5;
    float* wt_cs  = wt_c0  + 50 * taps5;

    dim3 b256(256);
    const int n_all = 18 * taps3 + 50 * taps5 + 50 * taps5 + 98 * taps7;
    wtrans_all<<<(n_all + 255) / 256, b256>>>(cv0_off_w, cvs_off_w, c0_off_w, cs_off_w, wt);

    cudaEventRecord(evRoot, 0);
    cudaStreamWaitEvent(s2, evRoot, 0);

    // ---- Branch 0 (stream 0): channels [0,64) ----
    offconv_gemm<3,1,1><<<dim3(16, 1, 2 * 16), b256>>>(x, 128, 0, wt_cv0, 18, 16, part0);
    combine_bilin<3,1,1><<<dim3(16, 9, 2), b256>>>(part0, cv0_off_b, 18, 16, bidx0, bw0);
    deform_apply<9><<<dim3(16, 32, 2), b256>>>(x, 128, 0, bidx0, bw0, cv0_w, t0a);

    offconv_gemm<5,3,6><<<dim3(16, 2, 2 * 8), b256>>>(t0a, 64, 0, wt_cvs, 50, 8, part0);
    combine_bilin<5,3,6><<<dim3(16, 25, 2), b256>>>(part0, cvs_off_b, 50, 8, bidx0, bw0);
    deform_apply<25><<<dim3(16, 32, 2), b256>>>(t0a, 64, 0, bidx0, bw0, cvs_w, t1a);

    conv1x1_gate_kernel<<<dim3(8, 64, 2), b256>>>(t1a, conv1_w, conv1_b, x, 0, out);

    // ---- Branch 1 (stream s2): channels [64,128) ----
    offconv_gemm<5,1,2><<<dim3(16, 2, 2 * 8), b256, 0, s2>>>(x, 128, 64, wt_c0, 50, 8, part1);
    combine_bilin<5,1,2><<<dim3(16, 25, 2), b256, 0, s2>>>(part1, c0_off_b, 50, 8, bidx1, bw1);
    deform_apply<25><<<dim3(16, 32, 2), b256, 0, s2>>>(x, 128, 64, bidx1, bw1, c0_w, t0b);

    offconv_gemm<7,3,9><<<dim3(16, 4, 2 * 4), b256, 0, s2>>>(t0b, 64, 0, wt_cs, 98, 4, part1);
    combine_bilin<7,3,9><<<dim3(16, 49, 2), b256, 0, s2>>>(part1, cs_off_b, 98, 4, bidx1, bw1);
    deform_apply<49><<<dim3(16, 32, 2), b256, 0, s2>>>(t0b, 64, 0, bidx1, bw1, cs_w, t1b);

    conv1x1_gate_kernel<<<dim3(8, 64, 2), b256, 0, s2>>>(t1b, conv2_w, conv2_b, x, 64, out);

    cudaEventRecord(evJoin, s2);
    cudaStreamWaitEvent(0, evJoin, 0);
}